// round 9
// baseline (speedup 1.0000x reference)
#include <cuda_runtime.h>
#include <cuda_bf16.h>
#include <cstdint>

#define B_  64
#define T_  512
#define H_  512
#define NCTA 128

// persist smem layout (bf16, padded rows: 520 = 512+8 -> conflict-free ldmatrix)
#define HB 520
#define SM_HH 0
#define SM_HL (64 * HB * 2)                 // 66560
#define SM_WH (2 * 64 * HB * 2)             // 133120
#define SM_WL (SM_WH + 32 * HB * 2)         // 166400
#define SM_XC (SM_WL + 32 * HB * 2)         // 199680: partial-sum exchange
#define PERSIST_SMEM (SM_XC + 8 * 32 * 8 * 4)   // +8192 = 207872

typedef unsigned long long u64;

// ---------------- scratch (device globals; no runtime allocation) ----------
__device__ float g_pre[2][T_][B_][2048];          // x@Wih^T + bias  (512 MB)
__device__ __nv_bfloat16 g_hh[2][2][B_][H_];      // h hi, ping-pong [phase][d][b][n]
__device__ __nv_bfloat16 g_hl[2][2][B_][H_];      // h lo
__device__ unsigned g_cnt[2 * 32];                // per-dir arrival counter
__device__ unsigned g_flag[2 * 32];               // per-dir epoch flag

// ---------------- helpers -----------------------------------------------------
__device__ __forceinline__ void ffma2(u64& d, u64 a, u64 b) {
    asm("fma.rn.f32x2 %0, %1, %2, %0;" : "+l"(d) : "l"(a), "l"(b));
}
__device__ __forceinline__ float hsum2(u64 v) {
    float lo, hi;
    asm("mov.b64 {%0,%1}, %2;" : "=f"(lo), "=f"(hi) : "l"(v));
    return lo + hi;
}
__device__ __forceinline__ void cp_async16(unsigned saddr, const void* gptr) {
    asm volatile("cp.async.cg.shared.global [%0], [%1], 16;" :: "r"(saddr), "l"(gptr));
}
__device__ __forceinline__ void cp_commit() { asm volatile("cp.async.commit_group;"); }
__device__ __forceinline__ void cp_wait0()  { asm volatile("cp.async.wait_group 0;" ::: "memory"); }
__device__ __forceinline__ unsigned ld_acq(const unsigned* p) {
    unsigned v;
    asm volatile("ld.global.acquire.gpu.u32 %0, [%1];" : "=r"(v) : "l"(p));
    return v;
}
__device__ __forceinline__ void st_rel(unsigned* p, unsigned v) {
    asm volatile("st.global.release.gpu.u32 [%0], %1;" :: "l"(p), "r"(v));
}
__device__ __forceinline__ float tanh_fast(float x) {
    float y;
    asm("tanh.approx.f32 %0, %1;" : "=f"(y) : "f"(x));
    return y;
}
__device__ __forceinline__ float sigmoid_fast(float x) {
    return fmaf(0.5f, tanh_fast(0.5f * x), 0.5f);
}
__device__ __forceinline__ void ldsm4(uint32_t r[4], uint32_t addr) {
    asm volatile("ldmatrix.sync.aligned.m8n8.x4.shared.b16 {%0,%1,%2,%3}, [%4];"
                 : "=r"(r[0]), "=r"(r[1]), "=r"(r[2]), "=r"(r[3]) : "r"(addr));
}
__device__ __forceinline__ void mma16816(float d[4], const uint32_t a[4],
                                         uint32_t b0, uint32_t b1) {
    asm volatile(
        "mma.sync.aligned.m16n8k16.row.col.f32.bf16.bf16.f32 "
        "{%0,%1,%2,%3}, {%4,%5,%6,%7}, {%8,%9}, {%0,%1,%2,%3};"
        : "+f"(d[0]), "+f"(d[1]), "+f"(d[2]), "+f"(d[3])
        : "r"(a[0]), "r"(a[1]), "r"(a[2]), "r"(a[3]), "r"(b0), "r"(b1));
}
__device__ __forceinline__ void split_bf16(float v, __nv_bfloat16& h, __nv_bfloat16& l) {
    h = __float2bfloat16_rn(v);
    l = __float2bfloat16_rn(v - __bfloat162float(h));
}

// ---------------- dummy (profiler slot alignment) -----------------------------
__global__ void dummy_k() {}

// ---------------- init: h0 split-scatter -------------------------------------
__global__ void init_k(const float* __restrict__ enc_h) {
    int i = blockIdx.x * blockDim.x + threadIdx.x;   // 0 .. 65535
    int n = i & 511;
    int b = (i >> 9) & 63;
    int d = i >> 15;
    __nv_bfloat16 h, l;
    split_bf16(enc_h[b * 1024 + d * 512 + n], h, l);
    g_hh[0][d][b][n] = h;
    g_hl[0][d][b][n] = l;
}

// ---------------- precompute GEMM (fp32 FFMA2, proven) -----------------------
__global__ __launch_bounds__(256) void pre_k(const float* __restrict__ x,
                                             const float* __restrict__ Wf,
                                             const float* __restrict__ bf,
                                             const float* __restrict__ Wb,
                                             const float* __restrict__ bb_) {
    const int d = blockIdx.z;
    const float* __restrict__ W    = d ? Wb  : Wf;
    const float* __restrict__ bias = d ? bb_ : bf;

    __shared__ float As[128][36];
    __shared__ float Bs[64][36];

    const int tid = threadIdx.x;
    const int m0  = blockIdx.y * 128;
    const int j0  = blockIdx.x * 64;
    const int tm  = tid >> 4;
    const int tn  = tid & 15;

    u64 acc[8][4];
#pragma unroll
    for (int i = 0; i < 8; i++)
#pragma unroll
        for (int j = 0; j < 4; j++) acc[i][j] = 0ull;

    for (int k0 = 0; k0 < 512; k0 += 32) {
#pragma unroll
        for (int i = 0; i < 4; i++) {
            int q   = tid + i * 256;
            int row = q >> 3;
            int kq  = (q & 7) * 4;
            int m   = m0 + row;
            int t   = m >> 6;
            int b   = m & 63;
            int tx  = d ? (511 - t) : t;
            *(float4*)&As[row][kq] =
                *(const float4*)(x + ((size_t)b * 512 + tx) * 512 + k0 + kq);
        }
#pragma unroll
        for (int i = 0; i < 2; i++) {
            int q   = tid + i * 256;
            int row = q >> 3;
            int kq  = (q & 7) * 4;
            *(float4*)&Bs[row][kq] =
                *(const float4*)(W + (size_t)(j0 + row) * 512 + k0 + kq);
        }
        __syncthreads();

#pragma unroll
        for (int kk = 0; kk < 32; kk += 4) {
            ulonglong2 a2[8], b2[4];
#pragma unroll
            for (int i = 0; i < 8; i++)
                a2[i] = *(const ulonglong2*)&As[tm * 8 + i][kk];
#pragma unroll
            for (int j = 0; j < 4; j++)
                b2[j] = *(const ulonglong2*)&Bs[tn * 4 + j][kk];
#pragma unroll
            for (int i = 0; i < 8; i++)
#pragma unroll
                for (int j = 0; j < 4; j++) {
                    ffma2(acc[i][j], a2[i].x, b2[j].x);
                    ffma2(acc[i][j], a2[i].y, b2[j].y);
                }
        }
        __syncthreads();
    }

    float4 bb4 = *(const float4*)(bias + j0 + tn * 4);
#pragma unroll
    for (int i = 0; i < 8; i++) {
        int m = m0 + tm * 8 + i;
        int t = m >> 6;
        int b = m & 63;
        float4 o;
        o.x = hsum2(acc[i][0]) + bb4.x;
        o.y = hsum2(acc[i][1]) + bb4.y;
        o.z = hsum2(acc[i][2]) + bb4.z;
        o.w = hsum2(acc[i][3]) + bb4.w;
        *(float4*)(&g_pre[d][t][b][j0 + tn * 4]) = o;
    }
}

// ---------------- persistent HMMA recurrence (split-k warp-groups) ------------
// 128 CTAs (1/SM), 512 threads = 2 warp-groups over k (WG0 k<256, WG1 k>=256).
// CTA = (d, 8 n-values). Cols c = nl*4 + gate. M=64 batch, N=32 per WG-warp set.
// Split-bf16 3-pass with 6 independent accumulator chains per warp.
__global__ __launch_bounds__(512, 1) void persist_k(const float* __restrict__ Whf,
                                                    const float* __restrict__ Whb,
                                                    const float* __restrict__ enc_c,
                                                    float* __restrict__ out) {
    extern __shared__ char sm[];
    const uint32_t sb = (uint32_t)__cvta_generic_to_shared(sm);
    __nv_bfloat16* Wh_s = (__nv_bfloat16*)(sm + SM_WH);
    __nv_bfloat16* Wl_s = (__nv_bfloat16*)(sm + SM_WL);
    float* xc = (float*)(sm + SM_XC);

    const int d   = blockIdx.x >> 6;
    const int n0  = (blockIdx.x & 63) * 8;
    const int tid = threadIdx.x;
    const int w   = tid >> 5;                // warp 0..15
    const int wg  = tid >> 8;                // k-half 0/1
    const int wl  = w & 7;                   // warp-in-group 0..7
    const int l   = tid & 31;
    const int tl  = tid & 255;               // thread-in-group
    const float* __restrict__ W = d ? Whb : Whf;

    unsigned* cnt  = &g_cnt[d * 32];
    unsigned* flag = &g_flag[d * 32];
    unsigned  base = 0;
    if (tid == 0) base = *flag;

    // ---- convert resident W tile to split bf16 in smem (rows c = nl*4+gate) --
    for (int i = tid; i < 32 * 512; i += 512) {
        int r = i >> 9;
        int k = i & 511;
        int j = (r & 3) * 512 + n0 + (r >> 2);
        __nv_bfloat16 h, lo;
        split_bf16(W[(size_t)j * 512 + k], h, lo);
        Wh_s[r * HB + k] = h;
        Wl_s[r * HB + k] = lo;
    }

    // ---- per-lane geometry ----
    const int m0 = (wl & 3) * 16;             // batch stripe
    const int jb = (wl >> 2) * 16;            // col base (2 n8 tiles)
    const uint32_t kbyte = (uint32_t)(wg * 256 * 2);   // k-half byte offset
    const uint32_t aoff = (uint32_t)(((m0 + (l & 15)) * HB + ((l >> 4) * 8)) * 2) + kbyte;
    const uint32_t boff = (uint32_t)(((jb + ((l >> 4) & 1) * 8 + (l & 7)) * HB
                                      + (((l >> 3) & 1) * 8)) * 2) + kbyte;
    const uint32_t aHb = sb + SM_HH + aoff;
    const uint32_t aLb = sb + SM_HL + aoff;
    const uint32_t bHb = sb + SM_WH + boff;
    const uint32_t bLb = sb + SM_WL + boff;

    const int b_out = m0 + (l >> 2) + ((l & 1) ? 8 : 0);
    const int nlb   = (jb >> 2) + ((l & 2) >> 1);

    float c_reg[2];
    if (wg == 0) {
#pragma unroll
        for (int t2 = 0; t2 < 2; t2++)
            c_reg[t2] = enc_c[b_out * 1024 + d * 512 + n0 + nlb + 2 * t2];
    }

    __syncthreads();

    for (int t = 0; t < 512; t++) {
        const int ph = t & 1;

        // ---- WG stages only its own k-half of h hi+lo (64 KB) ----
#pragma unroll
        for (int i = 0; i < 16; i++) {
            int q   = tl + i * 256;            // 0..4095
            int arr = q >> 11;                 // 0: hi, 1: lo
            int rem = q & 2047;
            int b   = rem >> 5;
            int kc  = (rem & 31) * 8 + wg * 256;
            const void* src = arr ? (const void*)&g_hl[ph][d][b][kc]
                                  : (const void*)&g_hh[ph][d][b][kc];
            uint32_t dst = sb + (arr ? SM_HL : SM_HH) + (uint32_t)((b * HB + kc) * 2);
            cp_async16(dst, src);
        }
        cp_commit();

        // ---- epilogue operand prefetch (WG0 = epilogue owner) ----
        float pre_r[2][4];
        if (wg == 0) {
#pragma unroll
            for (int t2 = 0; t2 < 2; t2++)
#pragma unroll
                for (int g = 0; g < 4; g++)
                    pre_r[t2][g] = __ldcs(&g_pre[d][t][b_out][g * 512 + n0 + nlb + 2 * t2]);
        }

        cp_wait0();
        asm volatile("bar.sync %0, 256;" :: "r"(wg + 1) : "memory");

        // ---- HMMA k-loop: 16 k16 steps, 6 independent acc chains ----
        float a_hh0[4] = {0, 0, 0, 0}, a_hh1[4] = {0, 0, 0, 0};
        float a_hl0[4] = {0, 0, 0, 0}, a_hl1[4] = {0, 0, 0, 0};
        float a_lh0[4] = {0, 0, 0, 0}, a_lh1[4] = {0, 0, 0, 0};
#pragma unroll 4
        for (int kk = 0; kk < 256; kk += 16) {
            uint32_t ah[4], al[4], bh[4], bl[4];
            ldsm4(ah, aHb + kk * 2);
            ldsm4(bh, bHb + kk * 2);
            ldsm4(al, aLb + kk * 2);
            ldsm4(bl, bLb + kk * 2);
            mma16816(a_hh0, ah, bh[0], bh[1]);
            mma16816(a_hh1, ah, bh[2], bh[3]);
            mma16816(a_hl0, ah, bl[0], bl[1]);
            mma16816(a_hl1, ah, bl[2], bl[3]);
            mma16816(a_lh0, al, bh[0], bh[1]);
            mma16816(a_lh1, al, bh[2], bh[3]);
        }
        float acc0[4], acc1[4];
#pragma unroll
        for (int i = 0; i < 4; i++) {
            acc0[i] = a_hh0[i] + a_hl0[i] + a_lh0[i];
            acc1[i] = a_hh1[i] + a_hl1[i] + a_lh1[i];
        }

        // ---- cross-WG partial exchange ----
        if (wg == 1) {
            float* p = xc + (wl * 32 + l) * 8;
#pragma unroll
            for (int i = 0; i < 4; i++) { p[i] = acc0[i]; p[4 + i] = acc1[i]; }
        }
        __syncthreads();

        if (wg == 0) {
            const float* p = xc + (wl * 32 + l) * 8;
#pragma unroll
            for (int i = 0; i < 4; i++) { acc0[i] += p[i]; acc1[i] += p[4 + i]; }

            // ---- gate exchange + fused epilogue ----
            const int odd = l & 1;
            const int tout = d ? (511 - t) : t;
            float* accs[2] = {acc0, acc1};
#pragma unroll
            for (int t2 = 0; t2 < 2; t2++) {
                float* a = accs[t2];
                float r0 = __shfl_xor_sync(0xFFFFFFFFu, odd ? a[0] : a[2], 1);
                float r1 = __shfl_xor_sync(0xFFFFFFFFu, odd ? a[1] : a[3], 1);
                float g0 = odd ? r0 : a[0];
                float g1 = odd ? r1 : a[1];
                float g2 = odd ? a[2] : r0;
                float g3 = odd ? a[3] : r1;

                float gi = pre_r[t2][0] + g0;
                float gf = pre_r[t2][1] + g1;
                float gg = pre_r[t2][2] + g2;
                float go = pre_r[t2][3] + g3;
                float si = sigmoid_fast(gi);
                float sf = sigmoid_fast(gf);
                float tg = tanh_fast(gg);
                float so = sigmoid_fast(go);
                float c  = sf * c_reg[t2] + si * tg;
                float h  = so * tanh_fast(c);
                c_reg[t2] = c;

                const int n = n0 + nlb + 2 * t2;
                __nv_bfloat16 hh, hl;
                split_bf16(h, hh, hl);
                g_hh[ph ^ 1][d][b_out][n] = hh;
                g_hl[ph ^ 1][d][b_out][n] = hl;
                __stcs(&out[((size_t)b_out * 512 + tout) * 1024 + d * 512 + n], h);
                if (t == 511) {
                    __stcs(&out[33554432 + b_out * 1024 + d * 512 + n], h);
                    __stcs(&out[33554432 + 65536 + b_out * 1024 + d * 512 + n], c);
                }
            }
        }

        // ---- per-direction grid barrier (monotonic epochs) ----
        if (t < 511) {
            __threadfence();
            __syncthreads();
            if (tid == 0) {
                unsigned target = base + (unsigned)(t + 1);
                unsigned ticket = atomicAdd(cnt, 1u);
                if ((ticket & 63u) == 63u) {
                    st_rel(flag, target);
                } else {
                    while (ld_acq(flag) < target) __nanosleep(64);
                }
            }
            __syncthreads();
        }
    }
}

// ---------------- launch -----------------------------------------------------
extern "C" void kernel_launch(void* const* d_in, const int* in_sizes, int n_in,
                              void* d_out, int out_size) {
    const float* x     = (const float*)d_in[0];
    const float* enc_h = (const float*)d_in[1];
    const float* enc_c = (const float*)d_in[2];
    const float* Wih_f = (const float*)d_in[3];
    const float* Whh_f = (const float*)d_in[4];
    const float* b_f   = (const float*)d_in[5];
    const float* Wih_b = (const float*)d_in[6];
    const float* Whh_b = (const float*)d_in[7];
    const float* b_b   = (const float*)d_in[8];
    float* out = (float*)d_out;

    cudaFuncSetAttribute(persist_k, cudaFuncAttributeMaxDynamicSharedMemorySize,
                         PERSIST_SMEM);

    dummy_k<<<1, 32>>>();                  // slot alignment: slot5 = persist_k
    init_k<<<256, 256>>>(enc_h);

    dim3 gA(32, 256, 2);
    pre_k<<<gA, 256>>>(x, Wih_f, b_f, Wih_b, b_b);

    persist_k<<<NCTA, 512, PERSIST_SMEM>>>(Whh_f, Whh_b, enc_c, out);
}

// round 10
// speedup vs baseline: 1.1200x; 1.1200x over previous
#include <cuda_runtime.h>
#include <cuda_bf16.h>
#include <cstdint>

#define B_  64
#define T_  512
#define H_  512
#define NCTA 128

// padded h rows: 520 bf16 = 1040B -> conflict-free ldmatrix, and the whole
// [64][520] slice (66560B) is ONE contiguous bulk-copy block.
#define HB 520
#define HSLICE (B_ * HB * 2)                // 66560 bytes
#define SM_HH 0
#define SM_HL HSLICE                        // 66560
#define SM_WH (2 * HSLICE)                  // 133120
#define SM_WL (SM_WH + 32 * HB * 2)         // 166400
#define SM_MB (SM_WL + 32 * HB * 2)         // 199680 (mbarrier)
#define PERSIST_SMEM (SM_MB + 64)           // 199744

typedef unsigned long long u64;

// ---------------- scratch (device globals; no runtime allocation) ----------
__device__ float g_pre[2][T_][B_][2048];            // x@Wih^T + bias  (512 MB)
__device__ __align__(16) __nv_bfloat16 g_hh[2][2][B_][HB];   // h hi (padded rows)
__device__ __align__(16) __nv_bfloat16 g_hl[2][2][B_][HB];   // h lo
__device__ unsigned g_cnt[2 * 32];                  // per-dir arrival counter (monotonic)

// ---------------- helpers -----------------------------------------------------
__device__ __forceinline__ void ffma2(u64& d, u64 a, u64 b) {
    asm("fma.rn.f32x2 %0, %1, %2, %0;" : "+l"(d) : "l"(a), "l"(b));
}
__device__ __forceinline__ float hsum2(u64 v) {
    float lo, hi;
    asm("mov.b64 {%0,%1}, %2;" : "=f"(lo), "=f"(hi) : "l"(v));
    return lo + hi;
}
__device__ __forceinline__ unsigned ld_acq(const unsigned* p) {
    unsigned v;
    asm volatile("ld.global.acquire.gpu.u32 %0, [%1];" : "=r"(v) : "l"(p));
    return v;
}
__device__ __forceinline__ float tanh_fast(float x) {
    float y;
    asm("tanh.approx.f32 %0, %1;" : "=f"(y) : "f"(x));
    return y;
}
__device__ __forceinline__ float sigmoid_fast(float x) {
    return fmaf(0.5f, tanh_fast(0.5f * x), 0.5f);
}
__device__ __forceinline__ void ldsm4(uint32_t r[4], uint32_t addr) {
    asm volatile("ldmatrix.sync.aligned.m8n8.x4.shared.b16 {%0,%1,%2,%3}, [%4];"
                 : "=r"(r[0]), "=r"(r[1]), "=r"(r[2]), "=r"(r[3]) : "r"(addr));
}
__device__ __forceinline__ void mma16816(float d[4], const uint32_t a[4],
                                         uint32_t b0, uint32_t b1) {
    asm volatile(
        "mma.sync.aligned.m16n8k16.row.col.f32.bf16.bf16.f32 "
        "{%0,%1,%2,%3}, {%4,%5,%6,%7}, {%8,%9}, {%0,%1,%2,%3};"
        : "+f"(d[0]), "+f"(d[1]), "+f"(d[2]), "+f"(d[3])
        : "r"(a[0]), "r"(a[1]), "r"(a[2]), "r"(a[3]), "r"(b0), "r"(b1));
}
__device__ __forceinline__ void split_bf16(float v, __nv_bfloat16& h, __nv_bfloat16& l) {
    h = __float2bfloat16_rn(v);
    l = __float2bfloat16_rn(v - __bfloat162float(h));
}
__device__ __forceinline__ void mbar_init(uint32_t a, uint32_t cnt) {
    asm volatile("mbarrier.init.shared.b64 [%0], %1;" :: "r"(a), "r"(cnt) : "memory");
}
__device__ __forceinline__ void mbar_expect_tx(uint32_t a, uint32_t tx) {
    asm volatile("mbarrier.arrive.expect_tx.shared.b64 _, [%0], %1;"
                 :: "r"(a), "r"(tx) : "memory");
}
__device__ __forceinline__ void mbar_wait(uint32_t a, uint32_t ph) {
    asm volatile(
        "{\n\t.reg .pred P;\n\t"
        "W_%=:\n\t"
        "mbarrier.try_wait.parity.acquire.cta.shared::cta.b64 P, [%0], %1, 0x989680;\n\t"
        "@!P bra W_%=;\n\t}"
        :: "r"(a), "r"(ph) : "memory");
}
__device__ __forceinline__ void bulk_cp(uint32_t dst, const void* src, uint32_t bytes,
                                        uint32_t mbar) {
    asm volatile(
        "cp.async.bulk.shared::cluster.global.mbarrier::complete_tx::bytes "
        "[%0], [%1], %2, [%3];"
        :: "r"(dst), "l"(src), "r"(bytes), "r"(mbar) : "memory");
}

// ---------------- dummy (profiler slot alignment) -----------------------------
__global__ void dummy_k() {}

// ---------------- init: h0 split-scatter (padded layout) ----------------------
__global__ void init_k(const float* __restrict__ enc_h) {
    int i = blockIdx.x * blockDim.x + threadIdx.x;   // 0 .. 65535
    int n = i & 511;
    int b = (i >> 9) & 63;
    int d = i >> 15;
    __nv_bfloat16 h, l;
    split_bf16(enc_h[b * 1024 + d * 512 + n], h, l);
    g_hh[0][d][b][n] = h;
    g_hl[0][d][b][n] = l;
}

// ---------------- precompute GEMM (fp32 FFMA2, proven) -----------------------
__global__ __launch_bounds__(256) void pre_k(const float* __restrict__ x,
                                             const float* __restrict__ Wf,
                                             const float* __restrict__ bf,
                                             const float* __restrict__ Wb,
                                             const float* __restrict__ bb_) {
    const int d = blockIdx.z;
    const float* __restrict__ W    = d ? Wb  : Wf;
    const float* __restrict__ bias = d ? bb_ : bf;

    __shared__ float As[128][36];
    __shared__ float Bs[64][36];

    const int tid = threadIdx.x;
    const int m0  = blockIdx.y * 128;
    const int j0  = blockIdx.x * 64;
    const int tm  = tid >> 4;
    const int tn  = tid & 15;

    u64 acc[8][4];
#pragma unroll
    for (int i = 0; i < 8; i++)
#pragma unroll
        for (int j = 0; j < 4; j++) acc[i][j] = 0ull;

    for (int k0 = 0; k0 < 512; k0 += 32) {
#pragma unroll
        for (int i = 0; i < 4; i++) {
            int q   = tid + i * 256;
            int row = q >> 3;
            int kq  = (q & 7) * 4;
            int m   = m0 + row;
            int t   = m >> 6;
            int b   = m & 63;
            int tx  = d ? (511 - t) : t;
            *(float4*)&As[row][kq] =
                *(const float4*)(x + ((size_t)b * 512 + tx) * 512 + k0 + kq);
        }
#pragma unroll
        for (int i = 0; i < 2; i++) {
            int q   = tid + i * 256;
            int row = q >> 3;
            int kq  = (q & 7) * 4;
            *(float4*)&Bs[row][kq] =
                *(const float4*)(W + (size_t)(j0 + row) * 512 + k0 + kq);
        }
        __syncthreads();

#pragma unroll
        for (int kk = 0; kk < 32; kk += 4) {
            ulonglong2 a2[8], b2[4];
#pragma unroll
            for (int i = 0; i < 8; i++)
                a2[i] = *(const ulonglong2*)&As[tm * 8 + i][kk];
#pragma unroll
            for (int j = 0; j < 4; j++)
                b2[j] = *(const ulonglong2*)&Bs[tn * 4 + j][kk];
#pragma unroll
            for (int i = 0; i < 8; i++)
#pragma unroll
                for (int j = 0; j < 4; j++) {
                    ffma2(acc[i][j], a2[i].x, b2[j].x);
                    ffma2(acc[i][j], a2[i].y, b2[j].y);
                }
        }
        __syncthreads();
    }

    float4 bb4 = *(const float4*)(bias + j0 + tn * 4);
#pragma unroll
    for (int i = 0; i < 8; i++) {
        int m = m0 + tm * 8 + i;
        int t = m >> 6;
        int b = m & 63;
        float4 o;
        o.x = hsum2(acc[i][0]) + bb4.x;
        o.y = hsum2(acc[i][1]) + bb4.y;
        o.z = hsum2(acc[i][2]) + bb4.z;
        o.w = hsum2(acc[i][3]) + bb4.w;
        *(float4*)(&g_pre[d][t][b][j0 + tn * 4]) = o;
    }
}

// ---------------- persistent HMMA recurrence (bulk-copy staging) --------------
// 128 CTAs (1/SM), 256 threads. CTA = (d, 8 n-values); cols c = nl*4 + gate.
// h staged via 2 cp.async.bulk per step (issue-free); split-bf16 3-pass HMMA.
__global__ __launch_bounds__(256, 1) void persist_k(const float* __restrict__ Whf,
                                                    const float* __restrict__ Whb,
                                                    const float* __restrict__ enc_c,
                                                    float* __restrict__ out) {
    extern __shared__ char sm[];
    const uint32_t sb = (uint32_t)__cvta_generic_to_shared(sm);
    __nv_bfloat16* Wh_s = (__nv_bfloat16*)(sm + SM_WH);
    __nv_bfloat16* Wl_s = (__nv_bfloat16*)(sm + SM_WL);
    const uint32_t mbar = sb + SM_MB;

    const int d   = blockIdx.x >> 6;
    const int n0  = (blockIdx.x & 63) * 8;
    const int tid = threadIdx.x;
    const int w   = tid >> 5;               // warp 0..7
    const int l   = tid & 31;
    const float* __restrict__ W = d ? Whb : Whf;

    unsigned* cnt = &g_cnt[d * 32];
    unsigned  base = 0;
    if (tid == 0) base = ld_acq(cnt);       // monotonic epoch base (replay-safe)

    // ---- convert resident W tile to split bf16 in smem (rows c = nl*4+gate) --
    for (int i = tid; i < 32 * 512; i += 256) {
        int r = i >> 9;
        int k = i & 511;
        int j = (r & 3) * 512 + n0 + (r >> 2);
        __nv_bfloat16 h, lo;
        split_bf16(W[(size_t)j * 512 + k], h, lo);
        Wh_s[r * HB + k] = h;
        Wl_s[r * HB + k] = lo;
    }

    // ---- per-lane geometry (verified R8 layout) ----
    const int m0 = (w & 3) * 16;             // batch stripe
    const int jb = (w >> 2) * 16;            // col base (2 n8 tiles)
    const uint32_t aoff = (uint32_t)(((m0 + (l & 15)) * HB + ((l >> 4) * 8)) * 2);
    const uint32_t boff = (uint32_t)(((jb + ((l >> 4) & 1) * 8 + (l & 7)) * HB
                                      + (((l >> 3) & 1) * 8)) * 2);
    const uint32_t aHb = sb + SM_HH + aoff;
    const uint32_t aLb = sb + SM_HL + aoff;
    const uint32_t bHb = sb + SM_WH + boff;
    const uint32_t bLb = sb + SM_WL + boff;

    const int b_out = m0 + (l >> 2) + ((l & 1) ? 8 : 0);
    const int nlb   = (jb >> 2) + ((l & 2) >> 1);

    float c_reg[2];
#pragma unroll
    for (int t2 = 0; t2 < 2; t2++)
        c_reg[t2] = enc_c[b_out * 1024 + d * 512 + n0 + nlb + 2 * t2];

    if (tid == 0) mbar_init(mbar, 1);
    __syncthreads();

    // ---- g_pre register pipeline: load step 0 ----
    float pre_cur[2][4], pre_next[2][4];
#pragma unroll
    for (int t2 = 0; t2 < 2; t2++)
#pragma unroll
        for (int g = 0; g < 4; g++)
            pre_cur[t2][g] = __ldcs(&g_pre[d][0][b_out][g * 512 + n0 + nlb + 2 * t2]);

    int mph = 0;
    for (int t = 0; t < 512; t++) {
        const int ph = t & 1;

        // ---- stage h hi+lo: TWO bulk copies (one thread) ----
        if (tid == 0) {
            mbar_expect_tx(mbar, 2 * HSLICE);
            bulk_cp(sb + SM_HH, &g_hh[ph][d][0][0], HSLICE, mbar);
            bulk_cp(sb + SM_HL, &g_hl[ph][d][0][0], HSLICE, mbar);
        }

        // ---- prefetch NEXT step's pre-activations (full-step lookahead) ----
        if (t + 1 < 512) {
#pragma unroll
            for (int t2 = 0; t2 < 2; t2++)
#pragma unroll
                for (int g = 0; g < 4; g++)
                    pre_next[t2][g] =
                        __ldcs(&g_pre[d][t + 1][b_out][g * 512 + n0 + nlb + 2 * t2]);
        }

        mbar_wait(mbar, mph);
        mph ^= 1;

        // ---- HMMA k-loop: 32 k16 steps, 6 independent acc chains ----
        float a_hh0[4] = {0, 0, 0, 0}, a_hh1[4] = {0, 0, 0, 0};
        float a_hl0[4] = {0, 0, 0, 0}, a_hl1[4] = {0, 0, 0, 0};
        float a_lh0[4] = {0, 0, 0, 0}, a_lh1[4] = {0, 0, 0, 0};
#pragma unroll 4
        for (int kk = 0; kk < 512; kk += 16) {
            uint32_t ah[4], al[4], bh[4], bl[4];
            ldsm4(ah, aHb + kk * 2);
            ldsm4(bh, bHb + kk * 2);
            ldsm4(al, aLb + kk * 2);
            ldsm4(bl, bLb + kk * 2);
            mma16816(a_hh0, ah, bh[0], bh[1]);
            mma16816(a_hh1, ah, bh[2], bh[3]);
            mma16816(a_hl0, ah, bl[0], bl[1]);
            mma16816(a_hl1, ah, bl[2], bl[3]);
            mma16816(a_lh0, al, bh[0], bh[1]);
            mma16816(a_lh1, al, bh[2], bh[3]);
        }
        float acc0[4], acc1[4];
#pragma unroll
        for (int i = 0; i < 4; i++) {
            acc0[i] = a_hh0[i] + a_hl0[i] + a_lh0[i];
            acc1[i] = a_hh1[i] + a_hl1[i] + a_lh1[i];
        }

        // ---- gate exchange + fused epilogue (verified R8 pattern) ----
        const int odd = l & 1;
        const int tout = d ? (511 - t) : t;
        float* accs[2] = {acc0, acc1};
#pragma unroll
        for (int t2 = 0; t2 < 2; t2++) {
            float* a = accs[t2];
            float r0 = __shfl_xor_sync(0xFFFFFFFFu, odd ? a[0] : a[2], 1);
            float r1 = __shfl_xor_sync(0xFFFFFFFFu, odd ? a[1] : a[3], 1);
            float g0 = odd ? r0 : a[0];
            float g1 = odd ? r1 : a[1];
            float g2 = odd ? a[2] : r0;
            float g3 = odd ? a[3] : r1;

            float gi = pre_cur[t2][0] + g0;
            float gf = pre_cur[t2][1] + g1;
            float gg = pre_cur[t2][2] + g2;
            float go = pre_cur[t2][3] + g3;
            float si = sigmoid_fast(gi);
            float sf = sigmoid_fast(gf);
            float tg = tanh_fast(gg);
            float so = sigmoid_fast(go);
            float c  = sf * c_reg[t2] + si * tg;
            float h  = so * tanh_fast(c);
            c_reg[t2] = c;

            const int n = n0 + nlb + 2 * t2;
            __nv_bfloat16 hh, hl;
            split_bf16(h, hh, hl);
            g_hh[ph ^ 1][d][b_out][n] = hh;
            g_hl[ph ^ 1][d][b_out][n] = hl;
            __stcs(&out[((size_t)b_out * 512 + tout) * 1024 + d * 512 + n], h);
            if (t == 511) {
                __stcs(&out[33554432 + b_out * 1024 + d * 512 + n], h);
                __stcs(&out[33554432 + 65536 + b_out * 1024 + d * 512 + n], c);
            }
        }

        // ---- rotate pre pipeline ----
#pragma unroll
        for (int t2 = 0; t2 < 2; t2++)
#pragma unroll
            for (int g = 0; g < 4; g++) pre_cur[t2][g] = pre_next[t2][g];

        // ---- per-direction grid barrier (single counter, tight poll) ----
        if (t < 511) {
            __threadfence();
            __syncthreads();
            if (tid == 0) {
                atomicAdd(cnt, 1u);
                unsigned target = base + 64u * (unsigned)(t + 1);
                while (ld_acq(cnt) < target) {}
            }
            __syncthreads();
        }
    }
}

// ---------------- launch -----------------------------------------------------
extern "C" void kernel_launch(void* const* d_in, const int* in_sizes, int n_in,
                              void* d_out, int out_size) {
    const float* x     = (const float*)d_in[0];
    const float* enc_h = (const float*)d_in[1];
    const float* enc_c = (const float*)d_in[2];
    const float* Wih_f = (const float*)d_in[3];
    const float* Whh_f = (const float*)d_in[4];
    const float* b_f   = (const float*)d_in[5];
    const float* Wih_b = (const float*)d_in[6];
    const float* Whh_b = (const float*)d_in[7];
    const float* b_b   = (const float*)d_in[8];
    float* out = (float*)d_out;

    cudaFuncSetAttribute(persist_k, cudaFuncAttributeMaxDynamicSharedMemorySize,
                         PERSIST_SMEM);

    dummy_k<<<1, 32>>>();                  // slot alignment: slot5 = persist_k
    init_k<<<256, 256>>>(enc_h);

    dim3 gA(32, 256, 2);
    pre_k<<<gA, 256>>>(x, Wih_f, b_f, Wih_b, b_b);

    persist_k<<<NCTA, 256, PERSIST_SMEM>>>(Whh_f, Whh_b, enc_c, out);
}